// round 1
// baseline (speedup 1.0000x reference)
#include <cuda_runtime.h>

#define SEQ   4096
#define BATCH 64
#define INP   64
#define HID   256
#define G3    768      // 3*HID
#define NCTA  128      // persistent scan CTAs (<= 148 SMs -> co-resident)

// Scratch (static device allocations are the sanctioned workaround)
__device__ float d_xg[(size_t)SEQ * G3 * BATCH];   // [s][g][b]   805 MB
__device__ float d_hs[(size_t)SEQ * HID * BATCH];  // [s][j][b]   268 MB
__device__ unsigned int d_arrive;

__global__ void reset_kernel() { d_arrive = 0u; }

// ---------------------------------------------------------------------------
// Kernel A: xg[s][g][b] = sum_i x[s][b][i] * w_ih[g][i] + b_ih[g]
// block = (s, 64-wide g slice); 256 threads; x row cached in registers,
// w broadcast from smem (uniform address per warp -> conflict-free).
// ---------------------------------------------------------------------------
__global__ void __launch_bounds__(256) xg_kernel(const float* __restrict__ x,
                                                 const float* __restrict__ w_ih,
                                                 const float* __restrict__ b_ih) {
    __shared__ float xs[INP][BATCH + 1];   // [i][b], padded: conflict-free xs[i][b]
    __shared__ float ws[64][INP];          // [g_local][i]
    const int s   = blockIdx.x;
    const int g0  = blockIdx.y * 64;
    const int tid = threadIdx.x;

    const float* xsrc = x + (size_t)s * BATCH * INP;
    for (int idx = tid; idx < BATCH * INP; idx += 256) {
        int b = idx >> 6, i = idx & 63;    // consecutive tid -> consecutive i (coalesced)
        xs[i][b] = xsrc[idx];
    }
    const float* wsrc = w_ih + (size_t)g0 * INP;
    for (int idx = tid; idx < 64 * INP; idx += 256)
        ws[idx >> 6][idx & 63] = wsrc[idx];
    __syncthreads();

    const int b  = tid & 63;
    const int gg = tid >> 6;               // 0..3, uniform within a warp
    float xr[INP];
#pragma unroll
    for (int i = 0; i < INP; i++) xr[i] = xs[i][b];

    float acc[16];
#pragma unroll
    for (int u = 0; u < 16; u++) acc[u] = 0.0f;
    const int gb = gg * 16;
#pragma unroll
    for (int i4 = 0; i4 < INP / 4; i4++) {
#pragma unroll
        for (int u = 0; u < 16; u++) {
            float4 w4 = *(const float4*)&ws[gb + u][i4 * 4];
            acc[u] += w4.x * xr[i4 * 4 + 0];
            acc[u] += w4.y * xr[i4 * 4 + 1];
            acc[u] += w4.z * xr[i4 * 4 + 2];
            acc[u] += w4.w * xr[i4 * 4 + 3];
        }
    }
    float* dst = d_xg + ((size_t)s * G3 + g0) * BATCH;
#pragma unroll
    for (int u = 0; u < 16; u++) {
        int gl = gb + u;
        dst[(size_t)gl * BATCH + b] = acc[u] + b_ih[g0 + gl];
    }
}

// ---------------------------------------------------------------------------
// Kernel B: persistent GRU scan. 128 CTAs x 128 threads.
// CTA c owns hidden units j0=2c, j0+1 -> 6 w_hh rows (r,z,n per j) in smem.
// Per step: 6x64 dot-products of length 256 over h(t-1) read from L2
// (fresh addresses each step -> no staleness), smem reduce over 8 K-splits,
// pointwise GRU update, publish hs[t] slice, release-fence, arrival counter.
// ---------------------------------------------------------------------------
__global__ void __launch_bounds__(128) scan_kernel(const float* __restrict__ w_hh,
                                                   const float* __restrict__ b_hh) {
    __shared__ float ws[6][HID];           // local row r = jj*3 + gate
    __shared__ float red[8][6][BATCH];     // [ksplit][row][b]
    const int c   = blockIdx.x;
    const int j0  = c * 2;
    const int tid = threadIdx.x;

    for (int idx = tid; idx < 6 * HID; idx += 128) {
        int r  = idx >> 8;                 // /256
        int k  = idx & 255;
        int jj = r / 3, gam = r % 3;
        ws[r][k] = w_hh[((size_t)gam * HID + j0 + jj) * HID + k];
    }

    const int pb  = tid & 63;              // pointwise: batch
    const int pjj = tid >> 6;              // pointwise: local j (0/1)
    const int pj  = j0 + pjj;
    const float bh_r = b_hh[pj];
    const float bh_z = b_hh[HID + pj];
    const float bh_n = b_hh[2 * HID + pj];

    const int bq    = tid & 15;            // batch quad: b = bq*4 .. bq*4+3
    const int ks    = tid >> 4;            // k-split 0..7 (32 k each)
    const int kbase = ks * 32;

    __syncthreads();

    volatile unsigned int* arr = &d_arrive;

    for (int t = 0; t < SEQ; t++) {
        float acc[6][4];
#pragma unroll
        for (int r = 0; r < 6; r++)
#pragma unroll
            for (int d = 0; d < 4; d++) acc[r][d] = 0.0f;

        if (t > 0) {
            const unsigned int target = (unsigned int)t * NCTA;
            while (*arr < target) { }      // all threads spin (per-thread acquire)
            __threadfence();

            const float* hp = d_hs + (size_t)(t - 1) * HID * BATCH;
#pragma unroll
            for (int kk = 0; kk < 32; kk += 4) {
                const int k = kbase + kk;
                float4 h0 = *(const float4*)&hp[(k + 0) * BATCH + bq * 4];
                float4 h1 = *(const float4*)&hp[(k + 1) * BATCH + bq * 4];
                float4 h2 = *(const float4*)&hp[(k + 2) * BATCH + bq * 4];
                float4 h3 = *(const float4*)&hp[(k + 3) * BATCH + bq * 4];
#pragma unroll
                for (int r = 0; r < 6; r++) {
                    float4 w4 = *(const float4*)&ws[r][k];
                    acc[r][0] += w4.x * h0.x; acc[r][1] += w4.x * h0.y;
                    acc[r][2] += w4.x * h0.z; acc[r][3] += w4.x * h0.w;
                    acc[r][0] += w4.y * h1.x; acc[r][1] += w4.y * h1.y;
                    acc[r][2] += w4.y * h1.z; acc[r][3] += w4.y * h1.w;
                    acc[r][0] += w4.z * h2.x; acc[r][1] += w4.z * h2.y;
                    acc[r][2] += w4.z * h2.z; acc[r][3] += w4.z * h2.w;
                    acc[r][0] += w4.w * h3.x; acc[r][1] += w4.w * h3.y;
                    acc[r][2] += w4.w * h3.z; acc[r][3] += w4.w * h3.w;
                }
            }
        }
#pragma unroll
        for (int r = 0; r < 6; r++)
#pragma unroll
            for (int d = 0; d < 4; d++)
                red[ks][r][bq * 4 + d] = acc[r][d];
        __syncthreads();

        // pointwise GRU update (torch form: n = tanh(xn + r*(hn + bhh_n)))
        float sr = 0.0f, sz = 0.0f, sn = 0.0f;
#pragma unroll
        for (int q = 0; q < 8; q++) {
            sr += red[q][pjj * 3 + 0][pb];
            sz += red[q][pjj * 3 + 1][pb];
            sn += red[q][pjj * 3 + 2][pb];
        }
        const size_t xoff = (size_t)t * G3 * BATCH;
        const float xrv = d_xg[xoff + (size_t)pj * BATCH + pb];
        const float xzv = d_xg[xoff + (size_t)(HID + pj) * BATCH + pb];
        const float xnv = d_xg[xoff + (size_t)(2 * HID + pj) * BATCH + pb];
        const float hold = (t > 0) ? d_hs[((size_t)(t - 1) * HID + pj) * BATCH + pb] : 0.0f;

        const float rg = 1.0f / (1.0f + __expf(-(xrv + sr + bh_r)));
        const float zg = 1.0f / (1.0f + __expf(-(xzv + sz + bh_z)));
        const float ng = tanhf(xnv + rg * (sn + bh_n));
        const float hnew = (1.0f - zg) * ng + zg * hold;
        d_hs[((size_t)t * HID + pj) * BATCH + pb] = hnew;

        __threadfence();                   // release: every thread's STG visible
        __syncthreads();                   // also separates red reuse across steps
        if (tid == 0) atomicAdd(&d_arrive, 1u);
    }
}

// ---------------------------------------------------------------------------
// Kernel C: out[s][b] = sum_j fc_w[j] * hs[s][j][b] + fc_b
// ---------------------------------------------------------------------------
__global__ void __launch_bounds__(256) fc_kernel(const float* __restrict__ fc_w,
                                                 const float* __restrict__ fc_b,
                                                 float* __restrict__ out) {
    __shared__ float wsh[HID];
    __shared__ float red[4][BATCH];
    const int s   = blockIdx.x;
    const int tid = threadIdx.x;
    if (tid < HID) wsh[tid] = fc_w[tid];
    __syncthreads();
    const int b  = tid & 63;
    const int jc = tid >> 6;
    const float* hp = d_hs + (size_t)s * HID * BATCH;
    float sum = 0.0f;
#pragma unroll 8
    for (int j = jc * 64; j < jc * 64 + 64; j++)
        sum += wsh[j] * hp[(size_t)j * BATCH + b];
    red[jc][b] = sum;
    __syncthreads();
    if (tid < BATCH)
        out[(size_t)s * BATCH + tid] =
            red[0][tid] + red[1][tid] + red[2][tid] + red[3][tid] + fc_b[0];
}

extern "C" void kernel_launch(void* const* d_in, const int* in_sizes, int n_in,
                              void* d_out, int out_size) {
    const float* x    = (const float*)d_in[0];
    const float* w_ih = (const float*)d_in[1];
    const float* w_hh = (const float*)d_in[2];
    const float* b_ih = (const float*)d_in[3];
    const float* b_hh = (const float*)d_in[4];
    const float* fc_w = (const float*)d_in[5];
    const float* fc_b = (const float*)d_in[6];
    float* out = (float*)d_out;

    reset_kernel<<<1, 1>>>();                       // re-arm barrier each replay
    dim3 ga(SEQ, G3 / 64);
    xg_kernel<<<ga, 256>>>(x, w_ih, b_ih);          // input-side gate projections
    scan_kernel<<<NCTA, 128>>>(w_hh, b_hh);         // persistent sequential scan
    fc_kernel<<<SEQ, 256>>>(fc_w, fc_b, out);       // output head
}